// round 4
// baseline (speedup 1.0000x reference)
#include <cuda_runtime.h>
#include <math.h>
#include <stdint.h>

#define NN 50000
#define EE 800000
#define DD 128
#define TDIM 32
#define EDIM 160
#define AGGW 288            // 128 (alpha*h) + 128 (alpha*msg) + 32 (alpha*timeenc)
#define KUPD 416            // 128 (h via A) + 288 (agg via [Wv|We])
#define EPSI 0.1f
#define GAMMA_C 0.1f
#define INV_SQRT_D 0.08838834764831843f

// ---------------- scratch (static device arrays; allocation-free) ----------------
__device__ float    g_h[NN * DD];
__device__ float    g_q[NN * DD];
__device__ float    g_k[NN * DD];
__device__ float    g_qe[NN * 256];          // qe[n,0:160] = We^T q ; [n,160] = q.be ; rest 0
__device__ float    g_agg[(size_t)NN * AGGW];
__device__ float    g_logit[EE];
__device__ unsigned g_segmax[NN];
__device__ float    g_segsum[NN];
__device__ int      g_src[EE];
__device__ int      g_dst[EE];
__device__ float    g_relt[EE];
__device__ int      g_is64;
__device__ float    g_W2[256 * DD];          // rows 0..159: We^T ; row 160: be ; rest 0
__device__ float    g_Wu[DD * KUPD];         // [col][ A(128) | Wv(128) | We(160) ]
__device__ float    g_bvbe[DD];

// ---------------- helpers ----------------
__device__ __forceinline__ unsigned f2o(float f) {
    unsigned u = __float_as_uint(f);
    return (u & 0x80000000u) ? ~u : (u | 0x80000000u);
}
__device__ __forceinline__ float o2f(unsigned u) {
    return (u & 0x80000000u) ? __uint_as_float(u & 0x7fffffffu) : __uint_as_float(~u);
}

// ---------------- edge-index dtype detection + conversion (+ rel_t) ----------------
__global__ void detect_kernel(const void* ei) {
    const unsigned* w = (const unsigned*)ei;
    __shared__ int nz;
    if (threadIdx.x == 0) nz = 0;
    __syncthreads();
    for (int i = threadIdx.x; i < 2048; i += 256)
        if (w[2 * i + 1] != 0u) nz = 1;
    __syncthreads();
    if (threadIdx.x == 0) g_is64 = (nz == 0) ? 1 : 0;
}

__global__ void convert_kernel(const void* ei, const float* __restrict__ lastup,
                               const float* __restrict__ tarr) {
    int i = blockIdx.x * 256 + threadIdx.x;
    if (i >= EE) return;
    int s, d;
    if (g_is64) {
        const long long* p = (const long long*)ei;
        s = (int)p[i]; d = (int)p[(size_t)EE + i];
    } else {
        const int* p = (const int*)ei;
        s = p[i]; d = p[EE + i];
    }
    g_src[i] = s; g_dst[i] = d;
    g_relt[i] = fabsf(lastup[s] - tarr[i]);
}

// ---------------- one-time weight preparation ----------------
__global__ void build_W2_kernel(const float* __restrict__ We, const float* __restrict__ be) {
    int j = blockIdx.x, t = threadIdx.x;          // j: 0..255, t: 0..127
    float v = 0.f;
    if (j < EDIM)       v = We[t * EDIM + j];
    else if (j == EDIM) v = be[t];
    g_W2[j * DD + t] = v;
}

__global__ void build_Wu_kernel(const float* __restrict__ Wa, const float* __restrict__ Wv,
                                const float* __restrict__ We) {
    int col = blockIdx.x, k = threadIdx.x;        // col: 0..127, k: 0..415
    float v;
    if (k < 128) {
        v = Wa[col * DD + k] - Wa[k * DD + col];
        if (k == col) v -= GAMMA_C;
    } else if (k < 256) {
        v = Wv[col * DD + (k - 128)];
    } else {
        v = We[col * EDIM + (k - 256)];
    }
    g_Wu[col * KUPD + k] = v;
}

__global__ void build_bvbe_kernel(const float* __restrict__ bv, const float* __restrict__ be) {
    int i = threadIdx.x;
    g_bvbe[i] = bv[i] + be[i];
}

// ---------------- generic 128-col GEMM: C[M,128] = A[M,K] @ W[128,K]^T + bias ----------------
__global__ __launch_bounds__(256, 2) void gemm128(
    const float* __restrict__ A, const float* __restrict__ W,
    const float* __restrict__ bias, float* __restrict__ C,
    int M, int K)
{
    __shared__ float sA[16][128];
    __shared__ float sW[16][128];
    const int t = threadIdx.x;
    const int m0 = blockIdx.x * 128;
    const int tx = t & 15;
    const int ty = t >> 4;
    const int lm = t >> 2;
    const int ls = t & 3;

    float acc[8][8];
#pragma unroll
    for (int i = 0; i < 8; i++)
#pragma unroll
        for (int j = 0; j < 8; j++) acc[i][j] = 0.f;

#pragma unroll 1
    for (int kc = 0; kc < K; kc += 16) {
#pragma unroll
        for (int h = 0; h < 2; h++) {
            int m = h * 64 + lm;
            int row = m0 + m;
            float4 v = make_float4(0.f, 0.f, 0.f, 0.f);
            if (row < M) v = *(const float4*)(A + (size_t)row * K + kc + ls * 4);
            sA[ls * 4 + 0][m] = v.x; sA[ls * 4 + 1][m] = v.y;
            sA[ls * 4 + 2][m] = v.z; sA[ls * 4 + 3][m] = v.w;
        }
#pragma unroll
        for (int h = 0; h < 2; h++) {
            int n = h * 64 + lm;
            float4 v = *(const float4*)(W + (size_t)n * K + kc + ls * 4);
            sW[ls * 4 + 0][n] = v.x; sW[ls * 4 + 1][n] = v.y;
            sW[ls * 4 + 2][n] = v.z; sW[ls * 4 + 3][n] = v.w;
        }
        __syncthreads();
#pragma unroll
        for (int k = 0; k < 16; k++) {
            float4 a0 = *(const float4*)&sA[k][ty * 4];
            float4 a1 = *(const float4*)&sA[k][ty * 4 + 64];
            float4 w0 = *(const float4*)&sW[k][tx * 4];
            float4 w1 = *(const float4*)&sW[k][tx * 4 + 64];
            float av[8] = {a0.x, a0.y, a0.z, a0.w, a1.x, a1.y, a1.z, a1.w};
            float wv[8] = {w0.x, w0.y, w0.z, w0.w, w1.x, w1.y, w1.z, w1.w};
#pragma unroll
            for (int i = 0; i < 8; i++)
#pragma unroll
                for (int j = 0; j < 8; j++) acc[i][j] = fmaf(av[i], wv[j], acc[i][j]);
        }
        __syncthreads();
    }

#pragma unroll
    for (int i = 0; i < 8; i++) {
        int row = m0 + ((i < 4) ? (ty * 4 + i) : (64 + ty * 4 + (i - 4)));
        if (row >= M) continue;
#pragma unroll
        for (int j = 0; j < 8; j++) {
            int col = (j < 4) ? (tx * 4 + j) : (64 + tx * 4 + (j - 4));
            C[(size_t)row * 128 + col] = acc[i][j] + bias[col];
        }
    }
}

// ---------------- qe GEMM: qe[N,256] = q[N,128] @ g_W2[256,128]^T (no bias) ----------------
__global__ __launch_bounds__(256, 2) void gemm_qe(int M)
{
    __shared__ float sA[16][128];
    __shared__ float sW[16][128];
    const int t = threadIdx.x;
    const int m0 = blockIdx.x * 128;
    const int n0 = blockIdx.y * 128;
    const int tx = t & 15;
    const int ty = t >> 4;
    const int lm = t >> 2;
    const int ls = t & 3;

    float acc[8][8];
#pragma unroll
    for (int i = 0; i < 8; i++)
#pragma unroll
        for (int j = 0; j < 8; j++) acc[i][j] = 0.f;

#pragma unroll 1
    for (int kc = 0; kc < 128; kc += 16) {
#pragma unroll
        for (int h = 0; h < 2; h++) {
            int m = h * 64 + lm;
            int row = m0 + m;
            float4 v = make_float4(0.f, 0.f, 0.f, 0.f);
            if (row < M) v = *(const float4*)(g_q + (size_t)row * 128 + kc + ls * 4);
            sA[ls * 4 + 0][m] = v.x; sA[ls * 4 + 1][m] = v.y;
            sA[ls * 4 + 2][m] = v.z; sA[ls * 4 + 3][m] = v.w;
        }
#pragma unroll
        for (int h = 0; h < 2; h++) {
            int n = h * 64 + lm;
            float4 v = *(const float4*)(g_W2 + (size_t)(n0 + n) * 128 + kc + ls * 4);
            sW[ls * 4 + 0][n] = v.x; sW[ls * 4 + 1][n] = v.y;
            sW[ls * 4 + 2][n] = v.z; sW[ls * 4 + 3][n] = v.w;
        }
        __syncthreads();
#pragma unroll
        for (int k = 0; k < 16; k++) {
            float4 a0 = *(const float4*)&sA[k][ty * 4];
            float4 a1 = *(const float4*)&sA[k][ty * 4 + 64];
            float4 w0 = *(const float4*)&sW[k][tx * 4];
            float4 w1 = *(const float4*)&sW[k][tx * 4 + 64];
            float av[8] = {a0.x, a0.y, a0.z, a0.w, a1.x, a1.y, a1.z, a1.w};
            float wv[8] = {w0.x, w0.y, w0.z, w0.w, w1.x, w1.y, w1.z, w1.w};
#pragma unroll
            for (int i = 0; i < 8; i++)
#pragma unroll
                for (int j = 0; j < 8; j++) acc[i][j] = fmaf(av[i], wv[j], acc[i][j]);
        }
        __syncthreads();
    }

#pragma unroll
    for (int i = 0; i < 8; i++) {
        int row = m0 + ((i < 4) ? (ty * 4 + i) : (64 + ty * 4 + (i - 4)));
        if (row >= M) continue;
#pragma unroll
        for (int j = 0; j < 8; j++) {
            int col = (j < 4) ? (tx * 4 + j) : (64 + tx * 4 + (j - 4));
            g_qe[(size_t)row * 256 + n0 + col] = acc[i][j];
        }
    }
}

// ---------------- update GEMM: h' = h + eps*tanh( [h|agg] @ Wu^T + b_anti (+bvbe) ) ----------------
__global__ __launch_bounds__(256, 2) void gemm_upd(
    const float* __restrict__ b_anti, float* __restrict__ C, int M)
{
    __shared__ float sA[16][128];
    __shared__ float sW[16][128];
    const int t = threadIdx.x;
    const int m0 = blockIdx.x * 128;
    const int tx = t & 15;
    const int ty = t >> 4;
    const int lm = t >> 2;
    const int ls = t & 3;

    float acc[8][8];
#pragma unroll
    for (int i = 0; i < 8; i++)
#pragma unroll
        for (int j = 0; j < 8; j++) acc[i][j] = 0.f;

#pragma unroll 1
    for (int kc = 0; kc < KUPD; kc += 16) {
#pragma unroll
        for (int h = 0; h < 2; h++) {
            int m = h * 64 + lm;
            int row = m0 + m;
            float4 v = make_float4(0.f, 0.f, 0.f, 0.f);
            if (row < M) {
                if (kc < 128)
                    v = *(const float4*)(g_h + (size_t)row * 128 + kc + ls * 4);
                else
                    v = *(const float4*)(g_agg + (size_t)row * AGGW + (kc - 128) + ls * 4);
            }
            sA[ls * 4 + 0][m] = v.x; sA[ls * 4 + 1][m] = v.y;
            sA[ls * 4 + 2][m] = v.z; sA[ls * 4 + 3][m] = v.w;
        }
#pragma unroll
        for (int h = 0; h < 2; h++) {
            int n = h * 64 + lm;
            float4 v = *(const float4*)(g_Wu + (size_t)n * KUPD + kc + ls * 4);
            sW[ls * 4 + 0][n] = v.x; sW[ls * 4 + 1][n] = v.y;
            sW[ls * 4 + 2][n] = v.z; sW[ls * 4 + 3][n] = v.w;
        }
        __syncthreads();
#pragma unroll
        for (int k = 0; k < 16; k++) {
            float4 a0 = *(const float4*)&sA[k][ty * 4];
            float4 a1 = *(const float4*)&sA[k][ty * 4 + 64];
            float4 w0 = *(const float4*)&sW[k][tx * 4];
            float4 w1 = *(const float4*)&sW[k][tx * 4 + 64];
            float av[8] = {a0.x, a0.y, a0.z, a0.w, a1.x, a1.y, a1.z, a1.w};
            float wv[8] = {w0.x, w0.y, w0.z, w0.w, w1.x, w1.y, w1.z, w1.w};
#pragma unroll
            for (int i = 0; i < 8; i++)
#pragma unroll
                for (int j = 0; j < 8; j++) acc[i][j] = fmaf(av[i], wv[j], acc[i][j]);
        }
        __syncthreads();
    }

#pragma unroll
    for (int i = 0; i < 8; i++) {
        int row = m0 + ((i < 4) ? (ty * 4 + i) : (64 + ty * 4 + (i - 4)));
        if (row >= M) continue;
        float hasE = (g_segsum[row] != 0.f) ? 1.f : 0.f;
#pragma unroll
        for (int j = 0; j < 8; j++) {
            int col = (j < 4) ? (tx * 4 + j) : (64 + tx * 4 + (j - 4));
            float val = acc[i][j] + b_anti[col] + hasE * g_bvbe[col];
            C[(size_t)row * 128 + col] =
                g_h[(size_t)row * 128 + col] + EPSI * tanhf(val);
        }
    }
}

// ---------------- per-iteration edge kernels ----------------
__global__ void init_kernel() {
    int i = blockIdx.x * 256 + threadIdx.x;
    if (i < NN * AGGW) g_agg[i] = 0.f;
    if (i < NN) { g_segmax[i] = 0u; g_segsum[i] = 0.f; }
}

// warp per edge: logit = (q[dst].k[src] + qe_m[dst].msg + qe_t[dst].cos(...) + qbe[dst]) / sqrt(d)
__global__ void logits_kernel(const float* __restrict__ msg,
                              const float* __restrict__ te_w,
                              const float* __restrict__ te_b) {
    int gtid = blockIdx.x * 256 + threadIdx.x;
    int e = gtid >> 5;
    int lane = gtid & 31;
    if (e >= EE) return;
    int s = g_src[e], d = g_dst[e];
    float4 qv = *(const float4*)(g_q + (size_t)d * 128 + lane * 4);
    float4 kv = *(const float4*)(g_k + (size_t)s * 128 + lane * 4);
    float4 mv;
    {
        const float4* mp = (const float4*)(msg + (size_t)e * 128) + lane;
        mv = __ldcs(mp);
    }
    float4 qm = *(const float4*)(g_qe + (size_t)d * 256 + lane * 4);
    float qt  = g_qe[(size_t)d * 256 + 128 + lane];
    float r   = g_relt[e];
    float ct  = cosf(r * te_w[lane] + te_b[lane]);

    float dot = qv.x * kv.x + qv.y * kv.y + qv.z * kv.z + qv.w * kv.w
              + qm.x * mv.x + qm.y * mv.y + qm.z * mv.z + qm.w * mv.w
              + qt * ct;
#pragma unroll
    for (int o = 16; o > 0; o >>= 1) dot += __shfl_xor_sync(0xffffffffu, dot, o);
    if (lane == 0) {
        float lg = (dot + g_qe[(size_t)d * 256 + 160]) * INV_SQRT_D;
        g_logit[e] = lg;
        atomicMax(&g_segmax[d], f2o(lg));
    }
}

__global__ void expsum_kernel() {
    int i = blockIdx.x * 256 + threadIdx.x;
    if (i >= EE) return;
    int d = g_dst[i];
    float m = o2f(g_segmax[d]);
    float ex = expf(g_logit[i] - m);
    g_logit[i] = ex;
    atomicAdd(&g_segsum[d], ex);
}

// warp per edge: agg[dst] += alpha * [ h[src] | msg | timeenc ]
__global__ void scatter_kernel(const float* __restrict__ msg,
                               const float* __restrict__ te_w,
                               const float* __restrict__ te_b) {
    int gtid = blockIdx.x * 256 + threadIdx.x;
    int e = gtid >> 5;
    int lane = gtid & 31;
    if (e >= EE) return;
    int s = g_src[e], d = g_dst[e];
    float alpha = g_logit[e] / g_segsum[d];

    float4 hv = *(const float4*)(g_h + (size_t)s * 128 + lane * 4);
    float4 mv;
    {
        const float4* mp = (const float4*)(msg + (size_t)e * 128) + lane;
        mv = __ldcs(mp);
    }
    float* base = g_agg + (size_t)d * AGGW;
    {
        float x0 = hv.x * alpha, x1 = hv.y * alpha, x2 = hv.z * alpha, x3 = hv.w * alpha;
        asm volatile("red.global.add.v4.f32 [%0], {%1,%2,%3,%4};"
                     :: "l"(base + lane * 4), "f"(x0), "f"(x1), "f"(x2), "f"(x3) : "memory");
    }
    {
        float x0 = mv.x * alpha, x1 = mv.y * alpha, x2 = mv.z * alpha, x3 = mv.w * alpha;
        asm volatile("red.global.add.v4.f32 [%0], {%1,%2,%3,%4};"
                     :: "l"(base + 128 + lane * 4), "f"(x0), "f"(x1), "f"(x2), "f"(x3) : "memory");
    }
    if (lane < 8) {
        float r = g_relt[e];
        int j = lane * 4;
        float c0 = cosf(r * te_w[j + 0] + te_b[j + 0]) * alpha;
        float c1 = cosf(r * te_w[j + 1] + te_b[j + 1]) * alpha;
        float c2 = cosf(r * te_w[j + 2] + te_b[j + 2]) * alpha;
        float c3 = cosf(r * te_w[j + 3] + te_b[j + 3]) * alpha;
        asm volatile("red.global.add.v4.f32 [%0], {%1,%2,%3,%4};"
                     :: "l"(base + 256 + j), "f"(c0), "f"(c1), "f"(c2), "f"(c3) : "memory");
    }
}

// ---------------- launch ----------------
extern "C" void kernel_launch(void* const* d_in, const int* in_sizes, int n_in,
                              void* d_out, int out_size)
{
    const float* x      = (const float*)d_in[0];
    const float* lastup = (const float*)d_in[1];
    const float* tarr   = (const float*)d_in[2];
    const float* msg    = (const float*)d_in[3];
    const void*  ei     = d_in[4];
    const float* enc_W  = (const float*)d_in[5];
    const float* enc_b  = (const float*)d_in[6];
    const float* te_w   = (const float*)d_in[7];
    const float* te_b   = (const float*)d_in[8];
    const float* Wq     = (const float*)d_in[9];
    const float* bq     = (const float*)d_in[10];
    const float* Wk     = (const float*)d_in[11];
    const float* bk     = (const float*)d_in[12];
    const float* Wv     = (const float*)d_in[13];
    const float* bv     = (const float*)d_in[14];
    const float* We     = (const float*)d_in[15];
    const float* be     = (const float*)d_in[16];
    const float* Wa     = (const float*)d_in[17];
    const float* ba     = (const float*)d_in[18];
    float* out = (float*)d_out;

    float *ph, *pq, *pk;
    cudaGetSymbolAddress((void**)&ph, g_h);
    cudaGetSymbolAddress((void**)&pq, g_q);
    cudaGetSymbolAddress((void**)&pk, g_k);

    const int gemm_blocks = (NN + 127) / 128;          // 391
    const int warp_blocks = EE / 8;                    // 100000
    const int init_blocks = (NN * AGGW + 255) / 256;

    detect_kernel<<<1, 256>>>(ei);
    convert_kernel<<<(EE + 255) / 256, 256>>>(ei, lastup, tarr);
    build_W2_kernel<<<256, 128>>>(We, be);
    build_Wu_kernel<<<128, KUPD>>>(Wa, Wv, We);
    build_bvbe_kernel<<<1, 128>>>(bv, be);

    // h0 = x @ enc_W^T + enc_b
    gemm128<<<gemm_blocks, 256>>>(x, enc_W, enc_b, ph, NN, 256);

    for (int it = 0; it < 3; it++) {
        gemm128<<<gemm_blocks, 256>>>(ph, Wq, bq, pq, NN, 128);
        gemm128<<<gemm_blocks, 256>>>(ph, Wk, bk, pk, NN, 128);
        gemm_qe<<<dim3(gemm_blocks, 2), 256>>>(NN);
        init_kernel<<<init_blocks, 256>>>();
        logits_kernel<<<warp_blocks, 256>>>(msg, te_w, te_b);
        expsum_kernel<<<(EE + 255) / 256, 256>>>();
        scatter_kernel<<<warp_blocks, 256>>>(msg, te_w, te_b);
        gemm_upd<<<gemm_blocks, 256>>>(ba, (it == 2) ? out : ph, NN);
    }
}